// round 1
// baseline (speedup 1.0000x reference)
#include <cuda_runtime.h>
#include <math.h>

#define NMAX 50000
#define HID  32
#define DIN  128

// ---------------- scratch (static allocation; no cudaMalloc allowed) ----------------
__device__ __align__(128) float g_y1[NMAX * HID];    // x @ W1_l.T
__device__ __align__(128) float g_r1[NMAX * HID];    // x @ W1_r.T
__device__ __align__(128) float g_agg1[NMAX * HID];  // segment sum of y1 over edges
__device__ __align__(128) float g_deg[NMAX];
__device__ __align__(128) float g_z2[NMAX];          // h @ W2_l.T (scalar)
__device__ __align__(128) float g_r2[NMAX];          // h @ W2_r.T (scalar)
__device__ __align__(128) float g_agg2[NMAX];
__device__ int g_is64;

// ---------------- packed f32x2 helpers ----------------
__device__ __forceinline__ unsigned long long fma2(unsigned long long a,
                                                   unsigned long long b,
                                                   unsigned long long c) {
    unsigned long long d;
    asm("fma.rn.f32x2 %0, %1, %2, %3;" : "=l"(d) : "l"(a), "l"(b), "l"(c));
    return d;
}
__device__ __forceinline__ float hsum2(unsigned long long a) {
    float lo, hi;
    asm("mov.b64 {%0, %1}, %2;" : "=f"(lo), "=f"(hi) : "l"(a));
    return lo + hi;
}

__device__ __forceinline__ void red_add_v4(float* addr, float4 v) {
    asm volatile("red.global.add.v4.f32 [%0], {%1, %2, %3, %4};"
                 :: "l"(addr), "f"(v.x), "f"(v.y), "f"(v.z), "f"(v.w)
                 : "memory");
}

__device__ __forceinline__ void load_edge(const void* ei, int E, int e, int is64,
                                          int& s, int& d) {
    if (is64) {
        const long long* p = (const long long*)ei;
        s = (int)p[e];
        d = (int)p[E + e];
    } else {
        const int* p = (const int*)ei;
        s = p[e];
        d = p[E + e];
    }
}

// ---------------- kernel 0: int64 vs int32 edge dtype detection ----------------
// Node ids < 2^31, so if storage is little-endian int64 every odd int32 word is 0.
__global__ void k_detect(const unsigned int* ei32, int scan_n) {
    __shared__ int found;
    if (threadIdx.x == 0) found = 0;
    __syncthreads();
    for (int i = 1 + 2 * threadIdx.x; i < scan_n; i += 2 * blockDim.x)
        if (ei32[i] != 0u) found = 1;  // benign race
    __syncthreads();
    if (threadIdx.x == 0) g_is64 = (found == 0) ? 1 : 0;
}

// ---------------- kernel 1: zero scratch ----------------
__global__ void k_zero(int n) {
    int tot = n * HID;
    int stride = gridDim.x * blockDim.x;
    for (int i = blockIdx.x * blockDim.x + threadIdx.x; i < tot; i += stride)
        g_agg1[i] = 0.0f;
    for (int i = blockIdx.x * blockDim.x + threadIdx.x; i < n; i += stride) {
        g_deg[i] = 0.0f;
        g_agg2[i] = 0.0f;
    }
}

// ---------------- kernel 2: fused dense projections y1 = x@Wl.T, r1 = x@Wr.T ----------------
// Warp per node. Lane = output feature o (0..31). W tiles in smem, row padded to
// 33 float4 so lane-stride LDS.128 is conflict-free within each quarter-warp.
__global__ void __launch_bounds__(128) k_lin1(const float* __restrict__ x,
                                              const float* __restrict__ Wl,
                                              const float* __restrict__ Wr,
                                              int n) {
    __shared__ float4 swl[32 * 33];
    __shared__ float4 swr[32 * 33];
    __shared__ float4 sx[4][32];

    int tid = threadIdx.x;
    for (int i = tid; i < 32 * 32; i += 128) {
        int o = i >> 5, j = i & 31;
        swl[o * 33 + j] = ((const float4*)Wl)[i];
        swr[o * 33 + j] = ((const float4*)Wr)[i];
    }
    __syncthreads();

    int warp = tid >> 5, lane = tid & 31;
    int stride = gridDim.x * 4;
    int node = blockIdx.x * 4 + warp;

    const float4* x4 = (const float4*)x;
    float4 xv = make_float4(0.f, 0.f, 0.f, 0.f);
    if (node < n) xv = x4[node * 32 + lane];

    const ulonglong2* wl2 = (const ulonglong2*)(swl + lane * 33);
    const ulonglong2* wr2 = (const ulonglong2*)(swr + lane * 33);
    const ulonglong2* sx2 = (const ulonglong2*)(sx[warp]);

    while (node < n) {
        sx[warp][lane] = xv;
        __syncwarp();
        int next = node + stride;
        if (next < n) xv = x4[next * 32 + lane];  // prefetch next row

        unsigned long long aL0 = 0ull, aL1 = 0ull, aR0 = 0ull, aR1 = 0ull;
#pragma unroll
        for (int j = 0; j < 32; j++) {
            ulonglong2 xp = sx2[j];   // broadcast
            ulonglong2 wl = wl2[j];
            ulonglong2 wr = wr2[j];
            aL0 = fma2(xp.x, wl.x, aL0);
            aL1 = fma2(xp.y, wl.y, aL1);
            aR0 = fma2(xp.x, wr.x, aR0);
            aR1 = fma2(xp.y, wr.y, aR1);
        }
        g_y1[node * 32 + lane] = hsum2(aL0) + hsum2(aL1);
        g_r1[node * 32 + lane] = hsum2(aR0) + hsum2(aR1);
        __syncwarp();
        node = next;
    }
}

// ---------------- kernel 3: edge aggregation of y1 (32-dim) + degree ----------------
// 8 threads per edge: each handles one float4 chunk -> coalesced 128B gather +
// one red.global.add.v4.f32 scatter.
__global__ void k_edge1(const void* __restrict__ ei, int E) {
    int is64 = g_is64;
    int total = E * 8;
    int stride = gridDim.x * blockDim.x;
    for (int t = blockIdx.x * blockDim.x + threadIdx.x; t < total; t += stride) {
        int e = t >> 3, c = t & 7;
        int s, d;
        load_edge(ei, E, e, is64, s, d);
        float4 v = ((const float4*)g_y1)[s * 8 + c];
        red_add_v4(&g_agg1[d * 32 + c * 4], v);
        if (c == 0) atomicAdd(&g_deg[d], 1.0f);
    }
}

// ---------------- kernel 4: node update h=relu(...) fused with layer-2 projections ----------------
__global__ void __launch_bounds__(128) k_node1(const float* __restrict__ b1,
                                               const float* __restrict__ W2l,
                                               const float* __restrict__ W2r,
                                               int n) {
    int tid = threadIdx.x;
    int warp = tid >> 5, lane = tid & 31;
    int stride = gridDim.x * 4;
    for (int node = blockIdx.x * 4 + warp; node < n; node += stride) {
        float inv = 1.0f / fmaxf(g_deg[node], 1.0f);
        float h = fmaf(g_agg1[node * 32 + lane], inv,
                       b1[lane] + g_r1[node * 32 + lane]);
        h = fmaxf(h, 0.0f);
        float zl = h * W2l[lane];
        float zr = h * W2r[lane];
#pragma unroll
        for (int o = 16; o; o >>= 1) {
            zl += __shfl_xor_sync(0xFFFFFFFFu, zl, o);
            zr += __shfl_xor_sync(0xFFFFFFFFu, zr, o);
        }
        if (lane == 0) {
            g_z2[node] = zl;
            g_r2[node] = zr;
        }
    }
}

// ---------------- kernel 5: scalar edge aggregation of z2 ----------------
__global__ void k_edge2(const void* __restrict__ ei, int E) {
    int is64 = g_is64;
    int stride = gridDim.x * blockDim.x;
    for (int e = blockIdx.x * blockDim.x + threadIdx.x; e < E; e += stride) {
        int s, d;
        load_edge(ei, E, e, is64, s, d);
        atomicAdd(&g_agg2[d], g_z2[s]);
    }
}

// ---------------- kernel 6: final sigmoid ----------------
__global__ void k_out(float* __restrict__ out, const float* __restrict__ b2, int n) {
    int i = blockIdx.x * blockDim.x + threadIdx.x;
    if (i < n) {
        float inv = 1.0f / fmaxf(g_deg[i], 1.0f);
        float v = fmaf(g_agg2[i], inv, b2[0] + g_r2[i]);
        out[i] = 1.0f / (1.0f + expf(-v));
    }
}

// ---------------- launch ----------------
extern "C" void kernel_launch(void* const* d_in, const int* in_sizes, int n_in,
                              void* d_out, int out_size) {
    const float* x   = (const float*)d_in[0];
    const void*  ei  = d_in[1];
    const float* W1l = (const float*)d_in[2];
    const float* b1  = (const float*)d_in[3];
    const float* W1r = (const float*)d_in[4];
    const float* W2l = (const float*)d_in[5];
    const float* b2  = (const float*)d_in[6];
    const float* W2r = (const float*)d_in[7];
    float* out = (float*)d_out;

    int n = in_sizes[0] / DIN;
    int E = in_sizes[1] / 2;
    if (n > NMAX) n = NMAX;

    k_detect<<<1, 256>>>((const unsigned int*)ei, 4096);
    k_zero<<<2048, 256>>>(n);
    k_lin1<<<592, 128>>>(x, W1l, W1r, n);
    k_edge1<<<(E * 8 + 255) / 256, 256>>>(ei, E);
    k_node1<<<(n + 3) / 4, 128>>>(b1, W2l, W2r, n);
    k_edge2<<<(E + 255) / 256, 256>>>(ei, E);
    k_out<<<(n + 255) / 256, 256>>>(out, b2, n);
}